// round 13
// baseline (speedup 1.0000x reference)
#include <cuda_runtime.h>
#include <cuda_fp16.h>
#include <cuda_bf16.h>
#include <cstdint>

typedef unsigned long long u64;
typedef unsigned int u32;

#define SEQ   4096
#define BATCH 2
#define EMB   768
#define NHEAD 12
#define HDIM  64
#define HALFW 256
#define MROWS (SEQ * BATCH)   // 8192

// q scaled by 0.125 * log2(e) so softmax can use exp2
#define QSCALE 0.18033688011112042f

// ---------------- device scratch ----------------
__device__ __nv_bfloat16 g_qkvh[3][(size_t)BATCH * NHEAD * SEQ * HDIM];
__device__ __nv_bfloat16 g_qkvl[3][(size_t)BATCH * NHEAD * SEQ * HDIM];
__device__ __half g_xh[(size_t)MROWS * EMB];            // X fp16
__device__ __half g_wt[3][(size_t)EMB * EMB];           // W^T fp16 [n][k]

// ---------------- PTX helpers ----------------
__device__ __forceinline__ u32 smem_u32(const void* p) {
    u32 a;
    asm("{ .reg .u64 t; cvta.to.shared.u64 t, %1; cvt.u32.u64 %0, t; }" : "=r"(a) : "l"(p));
    return a;
}
__device__ __forceinline__ void cp_async16(u32 dst, const void* src) {
    asm volatile("cp.async.cg.shared.global [%0], [%1], 16;" :: "r"(dst), "l"(src) : "memory");
}
__device__ __forceinline__ void cp_commit() {
    asm volatile("cp.async.commit_group;" ::: "memory");
}
template <int N>
__device__ __forceinline__ void cp_wait() {
    asm volatile("cp.async.wait_group %0;" :: "n"(N) : "memory");
}
__device__ __forceinline__ void ldmx4(u32* r, u32 addr) {
    asm volatile("ldmatrix.sync.aligned.m8n8.x4.shared.b16 {%0,%1,%2,%3}, [%4];"
                 : "=r"(r[0]), "=r"(r[1]), "=r"(r[2]), "=r"(r[3]) : "r"(addr));
}
__device__ __forceinline__ void ldmx4t(u32* r, u32 addr) {
    asm volatile("ldmatrix.sync.aligned.m8n8.x4.trans.shared.b16 {%0,%1,%2,%3}, [%4];"
                 : "=r"(r[0]), "=r"(r[1]), "=r"(r[2]), "=r"(r[3]) : "r"(addr));
}
// bf16 mma (attention, 3-term split)
__device__ __forceinline__ void mma16816(float* c, const u32* a, u32 b0, u32 b1) {
    asm volatile(
        "mma.sync.aligned.m16n8k16.row.col.f32.bf16.bf16.f32 "
        "{%0,%1,%2,%3}, {%4,%5,%6,%7}, {%8,%9}, {%0,%1,%2,%3};"
        : "+f"(c[0]), "+f"(c[1]), "+f"(c[2]), "+f"(c[3])
        : "r"(a[0]), "r"(a[1]), "r"(a[2]), "r"(a[3]), "r"(b0), "r"(b1));
}
// fp16 mma (GEMM)
__device__ __forceinline__ void mma16816h(float* c, const u32* a, u32 b0, u32 b1) {
    asm volatile(
        "mma.sync.aligned.m16n8k16.row.col.f32.f16.f16.f32 "
        "{%0,%1,%2,%3}, {%4,%5,%6,%7}, {%8,%9}, {%0,%1,%2,%3};"
        : "+f"(c[0]), "+f"(c[1]), "+f"(c[2]), "+f"(c[3])
        : "r"(a[0]), "r"(a[1]), "r"(a[2]), "r"(a[3]), "r"(b0), "r"(b1));
}
__device__ __forceinline__ u32 pack_bf(float lo, float hi) {
    u32 r;
    asm("cvt.rn.bf16x2.f32 %0, %1, %2;" : "=r"(r) : "f"(hi), "f"(lo));
    return r;
}
__device__ __forceinline__ void split_pair(float p0, float p1, u32& h, u32& l) {
    h = pack_bf(p0, p1);
    const float h0 = __uint_as_float(h << 16);
    const float h1 = __uint_as_float(h & 0xffff0000u);
    l = pack_bf(p0 - h0, p1 - h1);
}

// ---------------------------------------------------------------------------
__global__ __launch_bounds__(256) void conv_x_kernel(const float* __restrict__ X) {
    const size_t i = (size_t)blockIdx.x * 256 + threadIdx.x;
    if (i >= (size_t)MROWS * EMB) return;
    g_xh[i] = __float2half_rn(X[i]);
}

__global__ __launch_bounds__(256) void conv_w_kernel(
    const float* __restrict__ Wq, const float* __restrict__ Wk,
    const float* __restrict__ Wv)
{
    __shared__ float t[32][33];
    const int z = blockIdx.z;
    const float* W = (z == 0) ? Wq : (z == 1) ? Wk : Wv;
    const int n0 = blockIdx.x * 32;
    const int k0 = blockIdx.y * 32;
    const int tx = threadIdx.x, ty = threadIdx.y;
#pragma unroll
    for (int i = 0; i < 4; i++) {
        const int kk = ty + i * 8;
        t[kk][tx] = W[(size_t)(k0 + kk) * EMB + n0 + tx];
    }
    __syncthreads();
#pragma unroll
    for (int i = 0; i < 4; i++) {
        const int nn = ty + i * 8;
        g_wt[z][(size_t)(n0 + nn) * EMB + k0 + tx] = __float2half_rn(t[tx][nn]);
    }
}

// ---------------------------------------------------------------------------
// fp16 single-term QKV GEMM. CTA tile 256x64 (halves W L2 traffic vs 128x64),
// 256 threads / 8 warps (4M x 2N), warp tile 64x32 (R3-validated geometry).
// Epilogue writes bf16 hi/lo residual pairs (near-exact Q/K/V).
// ---------------------------------------------------------------------------
#define BK        32
#define ROWB      80
#define ATILE_B   (256 * ROWB)               // 20480
#define BTILE_B   (64 * ROWB)                // 5120
#define STAGE_B   (ATILE_B + BTILE_B)        // 25600
#define NSTAGE    3
#define GEMM_SMEM (NSTAGE * STAGE_B)         // 76800
#define NCHUNK    (EMB / BK)                 // 24
#define OFF_A     0
#define OFF_B     ATILE_B

__global__ __launch_bounds__(256)
void gemm_fp16_kernel(const float* __restrict__ bq, const float* __restrict__ bk_,
                      const float* __restrict__ bv)
{
    extern __shared__ __align__(1024) char smem[];
    __shared__ float bias_sh[64];

    const int tid = threadIdx.x;
    const int wid = tid >> 5;
    const int lid = tid & 31;
    const int wm = wid >> 1;        // 0..3 (64-row slab)
    const int wn = wid & 1;         // 0..1 (32-col slab)
    const int which = blockIdx.z;
    const int m0 = blockIdx.x * 256;
    const int n0 = blockIdx.y * 64;

    const u32 sb = smem_u32(smem);

    const float* bias = (which == 0) ? bq : (which == 1) ? bk_ : bv;
    if (tid < 64) bias_sh[tid] = bias[n0 + tid];

    const __half* srcA = g_xh + (size_t)m0 * EMB;
    const __half* srcB = g_wt[which] + (size_t)n0 * EMB;

    // A frag offsets (R3-validated x4 geometry), 4 m16 tiles per warp
    u32 aoff[4];
#pragma unroll
    for (int mi = 0; mi < 4; mi++)
        aoff[mi] = (u32)((wm * 64 + mi * 16 + (lid & 7) + ((lid >> 3) & 1) * 8) * ROWB
                         + (lid >> 4) * 16);
    u32 boff[2];
#pragma unroll
    for (int j = 0; j < 2; j++)
        boff[j] = (u32)((wn * 32 + j * 16 + ((lid >> 4) & 1) * 8 + (lid & 7)) * ROWB
                        + ((lid >> 3) & 1) * 16);

    float acc[4][4][4];
#pragma unroll
    for (int mi = 0; mi < 4; mi++)
#pragma unroll
        for (int ni = 0; ni < 4; ni++)
#pragma unroll
            for (int q = 0; q < 4; q++) acc[mi][ni][q] = 0.0f;

    // chunk: A 256 rows x 4 granules = 1024 (4/thread); B 64 x 4 = 256 (1/thread)
    auto load_chunk = [&](int c, int s) {
        const int k0 = c * BK;
        const u32 stage = sb + s * STAGE_B;
        const int row0 = tid >> 2;
        const int prt  = tid & 3;
#pragma unroll
        for (int i = 0; i < 4; i++) {
            const int row = row0 + i * 64;
            cp_async16(stage + OFF_A + row * ROWB + prt * 16,
                       srcA + (size_t)row * EMB + k0 + prt * 8);
        }
        cp_async16(stage + OFF_B + row0 * ROWB + prt * 16,
                   srcB + (size_t)row0 * EMB + k0 + prt * 8);
        cp_commit();
    };

    auto compute_chunk = [&](int s) {
        const u32 stage = sb + s * STAGE_B;
        const u32 aB = stage + OFF_A, bB = stage + OFF_B;
#pragma unroll
        for (int ks = 0; ks < 2; ks++) {
            const u32 kadv = ks * 32;
            u32 af[4][4], bf[2][4];
#pragma unroll
            for (int mi = 0; mi < 4; mi++) ldmx4(af[mi], aB + aoff[mi] + kadv);
#pragma unroll
            for (int j = 0; j < 2; j++)    ldmx4(bf[j], bB + boff[j] + kadv);
#pragma unroll
            for (int mi = 0; mi < 4; mi++)
#pragma unroll
                for (int ni = 0; ni < 4; ni++) {
                    const int j = ni >> 1, e = (ni & 1) * 2;
                    mma16816h(acc[mi][ni], af[mi], bf[j][e], bf[j][e + 1]);
                }
        }
    };

    load_chunk(0, 0);
    load_chunk(1, 1);
    for (int c = 0; c < NCHUNK; c++) {
        cp_wait<1>();
        __syncthreads();
        if (c + 2 < NCHUNK) load_chunk(c + 2, (c + 2) % NSTAGE);
        compute_chunk(c % NSTAGE);
    }
    __syncthreads();

    // epilogue: bias + scale (q carries log2e), split to bf16 hi/lo, scatter
    const float scale = (which == 0) ? QSCALE : 1.0f;
    const int row_in_q = lid >> 2;
    const int col_pair = (lid & 3) * 2;
    const int h = n0 >> 6;
#pragma unroll
    for (int mi = 0; mi < 4; mi++) {
#pragma unroll
        for (int ni = 0; ni < 4; ni++) {
            const int ncol = wn * 32 + ni * 8 + col_pair;
            const int d = (n0 + ncol) & 63;
            const float b0v = bias_sh[ncol], b1v = bias_sh[ncol + 1];
#pragma unroll
            for (int half = 0; half < 2; half++) {
                const int m = m0 + wm * 64 + mi * 16 + row_in_q + half * 8;
                const int s_ = m >> 1;
                const int b_ = m & 1;
                float bias0 = b0v, bias1 = b1v;
                const float v0 = (acc[mi][ni][half * 2 + 0] + bias0) * scale;
                const float v1 = (acc[mi][ni][half * 2 + 1] + bias1) * scale;
                u32 hpk, lpk;
                split_pair(v0, v1, hpk, lpk);
                const size_t idx = ((size_t)(b_ * NHEAD + h) * SEQ + s_) * HDIM + d;
                *(u32*)(g_qkvh[which] + idx) = hpk;
                *(u32*)(g_qkvl[which] + idx) = lpk;
            }
        }
    }
}

// ---------------------------------------------------------------------------
// Banded local attention — R10-proven 3-term bf16 split on scores AND PV.
// Only change: exp2f softmax (q pre-scaled by log2e).
// ---------------------------------------------------------------------------
#define AROWB   144
#define ATILE   (64 * AROWB)
#define AQ_B    (2 * ATILE)
#define ASTAGE  (4 * ATILE)
#define AT_SMEM (AQ_B + 2 * ASTAGE)          // 92160

__global__ __launch_bounds__(128, 2)
void attn_mma_kernel(float* __restrict__ out)
{
    extern __shared__ __align__(1024) char smem[];
    const int tid = threadIdx.x;
    const int wid = tid >> 5;
    const int lid = tid & 31;
    const int q0 = blockIdx.x * 64;
    const int h  = blockIdx.y;
    const int b  = blockIdx.z;
    const size_t bh = (size_t)(b * NHEAD + h) * SEQ * HDIM;

    const u32 sb = smem_u32(smem);

    int kt0 = q0 - HALFW; if (kt0 < 0) kt0 = 0;
    int kt1 = q0 + HALFW; if (kt1 > SEQ - 64) kt1 = SEQ - 64;
    const int T = (kt1 - kt0) / 64 + 1;

    auto load_q = [&] {
#pragma unroll
        for (int tq = 0; tq < 2; tq++) {
            const __nv_bfloat16* src =
                ((tq == 0) ? g_qkvh[0] : g_qkvl[0]) + bh + (size_t)q0 * HDIM;
            const u32 dstb = sb + tq * ATILE;
#pragma unroll
            for (int i = 0; i < 4; i++) {
                const int g = tid + i * 128;
                const int row = g >> 3, c = g & 7;
                cp_async16(dstb + row * AROWB + c * 16, src + row * HDIM + c * 8);
            }
        }
    };
    auto load_kv = [&](int t, int s) {
        const int kt = kt0 + t * 64;
        const u32 stb = sb + AQ_B + s * ASTAGE;
        const __nv_bfloat16* srcs[4] = {
            g_qkvh[1] + bh + (size_t)kt * HDIM, g_qkvl[1] + bh + (size_t)kt * HDIM,
            g_qkvh[2] + bh + (size_t)kt * HDIM, g_qkvl[2] + bh + (size_t)kt * HDIM };
#pragma unroll
        for (int tt = 0; tt < 4; tt++) {
            const u32 dstb = stb + tt * ATILE;
#pragma unroll
            for (int i = 0; i < 4; i++) {
                const int g = tid + i * 128;
                const int row = g >> 3, c = g & 7;
                cp_async16(dstb + row * AROWB + c * 16, srcs[tt] + row * HDIM + c * 8);
            }
        }
    };

    load_q();
    load_kv(0, 0);
    cp_commit();

    const u32 a_off = (u32)((wid * 16 + (lid & 7) + ((lid >> 3) & 1) * 8) * AROWB
                            + (lid >> 4) * 16);
    u32 kb_off[4];
#pragma unroll
    for (int p = 0; p < 4; p++)
        kb_off[p] = (u32)((16 * p + ((lid >> 4) & 1) * 8 + (lid & 7)) * AROWB
                          + ((lid >> 3) & 1) * 16);
    const u32 v_off = (u32)((lid & 15) * AROWB + (lid >> 4) * 16);

    u32 qf[2][4][4];
    float o[8][4];
    float m_r[2] = { -1e30f, -1e30f };
    float l_r[2] = { 0.0f, 0.0f };
#pragma unroll
    for (int ni = 0; ni < 8; ni++)
#pragma unroll
        for (int e = 0; e < 4; e++) o[ni][e] = 0.0f;

    const int r_lane = lid >> 2;
    const int c_lane = (lid & 3) * 2;

    for (int t = 0; t < T; t++) {
        if (t + 1 < T) {
            load_kv(t + 1, (t + 1) & 1);
            cp_commit();
            cp_wait<1>();
        } else {
            cp_wait<0>();
        }
        __syncthreads();

        if (t == 0) {
#pragma unroll
            for (int ks = 0; ks < 4; ks++) {
                ldmx4(qf[0][ks], sb + 0 * ATILE + a_off + ks * 32);
                ldmx4(qf[1][ks], sb + 1 * ATILE + a_off + ks * 32);
            }
        }

        const int kt = kt0 + t * 64;
        const u32 st = sb + AQ_B + (t & 1) * ASTAGE;
        const u32 kHi = st + 0 * ATILE, kLo = st + 1 * ATILE;
        const u32 vHi = st + 2 * ATILE, vLo = st + 3 * ATILE;

        // ---- scores: 3-term bf16 split ----
        float sc[8][4];
#pragma unroll
        for (int ni = 0; ni < 8; ni++)
#pragma unroll
            for (int e = 0; e < 4; e++) sc[ni][e] = 0.0f;

#pragma unroll
        for (int ks = 0; ks < 4; ks++) {
            u32 bh4[4][4], bl4[4][4];
#pragma unroll
            for (int p = 0; p < 4; p++) {
                ldmx4(bh4[p], kHi + kb_off[p] + ks * 32);
                ldmx4(bl4[p], kLo + kb_off[p] + ks * 32);
            }
#pragma unroll
            for (int p = 0; p < 4; p++) {
                mma16816(sc[2 * p + 0], qf[0][ks], bh4[p][0], bh4[p][1]);
                mma16816(sc[2 * p + 1], qf[0][ks], bh4[p][2], bh4[p][3]);
            }
#pragma unroll
            for (int p = 0; p < 4; p++) {
                mma16816(sc[2 * p + 0], qf[0][ks], bl4[p][0], bl4[p][1]);
                mma16816(sc[2 * p + 1], qf[0][ks], bl4[p][2], bl4[p][3]);
            }
#pragma unroll
            for (int p = 0; p < 4; p++) {
                mma16816(sc[2 * p + 0], qf[1][ks], bh4[p][0], bh4[p][1]);
                mma16816(sc[2 * p + 1], qf[1][ks], bh4[p][2], bh4[p][3]);
            }
        }

        // ---- band mask ----
        if (kt == q0 - HALFW || kt == q0 + HALFW) {
#pragma unroll
            for (int ni = 0; ni < 8; ni++)
#pragma unroll
                for (int e = 0; e < 4; e++) {
                    const int kc = kt + ni * 8 + c_lane + (e & 1);
                    const int qa = q0 + wid * 16 + r_lane + ((e >> 1) << 3);
                    const int d = kc - qa;
                    if (d < -HALFW || d > HALFW) sc[ni][e] = -3.0e38f;
                }
        }

        // ---- online softmax (base-2; q carries log2e) ----
        float mx0 = -3.0e38f, mx1 = -3.0e38f;
#pragma unroll
        for (int ni = 0; ni < 8; ni++) {
            mx0 = fmaxf(mx0, fmaxf(sc[ni][0], sc[ni][1]));
            mx1 = fmaxf(mx1, fmaxf(sc[ni][2], sc[ni][3]));
        }
        mx0 = fmaxf(mx0, __shfl_xor_sync(0xffffffffu, mx0, 1));
        mx0 = fmaxf(mx0, __shfl_xor_sync(0xffffffffu, mx0, 2));
        mx1 = fmaxf(mx1, __shfl_xor_sync(0xffffffffu, mx1, 1));
        mx1 = fmaxf(mx1, __shfl_xor_sync(0xffffffffu, mx1, 2));

        const float nm0 = fmaxf(m_r[0], mx0);
        const float nm1 = fmaxf(m_r[1], mx1);
        const float c0 = exp2f(m_r[0] - nm0);
        const float c1 = exp2f(m_r[1] - nm1);
        float s0 = 0.0f, s1 = 0.0f;
#pragma unroll
        for (int ni = 0; ni < 8; ni++) {
            sc[ni][0] = exp2f(sc[ni][0] - nm0); s0 += sc[ni][0];
            sc[ni][1] = exp2f(sc[ni][1] - nm0); s0 += sc[ni][1];
            sc[ni][2] = exp2f(sc[ni][2] - nm1); s1 += sc[ni][2];
            sc[ni][3] = exp2f(sc[ni][3] - nm1); s1 += sc[ni][3];
        }
        s0 += __shfl_xor_sync(0xffffffffu, s0, 1);
        s0 += __shfl_xor_sync(0xffffffffu, s0, 2);
        s1 += __shfl_xor_sync(0xffffffffu, s1, 1);
        s1 += __shfl_xor_sync(0xffffffffu, s1, 2);
        l_r[0] = l_r[0] * c0 + s0; m_r[0] = nm0;
        l_r[1] = l_r[1] * c1 + s1; m_r[1] = nm1;
#pragma unroll
        for (int ni = 0; ni < 8; ni++) {
            o[ni][0] *= c0; o[ni][1] *= c0;
            o[ni][2] *= c1; o[ni][3] *= c1;
        }

        // ---- PV: 3-term bf16 split (proven) ----
#pragma unroll
        for (int ks = 0; ks < 4; ks++) {
            u32 ph[4], pl[4];
            split_pair(sc[2 * ks + 0][0], sc[2 * ks + 0][1], ph[0], pl[0]);
            split_pair(sc[2 * ks + 0][2], sc[2 * ks + 0][3], ph[1], pl[1]);
            split_pair(sc[2 * ks + 1][0], sc[2 * ks + 1][1], ph[2], pl[2]);
            split_pair(sc[2 * ks + 1][2], sc[2 * ks + 1][3], ph[3], pl[3]);
            u32 vh4[4][4], vl4[4][4];
#pragma unroll
            for (int p = 0; p < 4; p++) {
                ldmx4t(vh4[p], vHi + v_off + ks * 16 * AROWB + p * 32);
                ldmx4t(vl4[p], vLo + v_off + ks * 16 * AROWB + p * 32);
            }
#pragma unroll
            for (int p = 0; p < 4; p++) {
                mma16816(o[2 * p + 0], ph, vh4[p][0], vh4[p][1]);
                mma16816(o[2 * p + 1], ph, vh4[p][2], vh4[p][3]);
            }
#pragma unroll
            for (int p = 0; p < 4; p++) {
                mma16816(o[2 * p + 0], ph, vl4[p][0], vl4[p][1]);
                mma16816(o[2 * p + 1], ph, vl4[p][2], vl4[p][3]);
            }
#pragma unroll
            for (int p = 0; p < 4; p++) {
                mma16816(o[2 * p + 0], pl, vh4[p][0], vh4[p][1]);
                mma16816(o[2 * p + 1], pl, vh4[p][2], vh4[p][3]);
            }
        }
        __syncthreads();
    }

    // ---- epilogue ----
    const float inv0 = 1.0f / l_r[0];
    const float inv1 = 1.0f / l_r[1];
    const int s_row0 = q0 + wid * 16 + r_lane;
#pragma unroll
    for (int ni = 0; ni < 8; ni++) {
        const int dcol = ni * 8 + c_lane;
        const size_t base = (size_t)b * EMB + h * HDIM + dcol;
        float2 r0, r1;
        r0.x = o[ni][0] * inv0; r0.y = o[ni][1] * inv0;
        r1.x = o[ni][2] * inv1; r1.y = o[ni][3] * inv1;
        *(float2*)(out + (size_t)s_row0 * (BATCH * EMB) + base) = r0;
        *(float2*)(out + (size_t)(s_row0 + 8) * (BATCH * EMB) + base) = r1;
    }
}

extern "C" void kernel_launch(void* const* d_in, const int* in_sizes, int n_in,
                              void* d_out, int out_size) {
    (void)in_sizes; (void)n_in; (void)out_size;
    const float* X  = (const float*)d_in[0];
    const float* Wq = (const float*)d_in[1];
    const float* bq = (const float*)d_in[2];
    const float* Wk = (const float*)d_in[3];
    const float* bk = (const float*)d_in[4];
    const float* Wv = (const float*)d_in[5];
    const float* bv = (const float*)d_in[6];
    float* out = (float*)d_out;

    static int attr_set = 0;
    if (!attr_set) {
        cudaFuncSetAttribute(gemm_fp16_kernel,
                             cudaFuncAttributeMaxDynamicSharedMemorySize, GEMM_SMEM);
        cudaFuncSetAttribute(attn_mma_kernel,
                             cudaFuncAttributeMaxDynamicSharedMemorySize, AT_SMEM);
        attr_set = 1;
    }

    conv_x_kernel<<<(MROWS * EMB + 255) / 256, 256>>>(X);
    conv_w_kernel<<<dim3(24, 24, 3), dim3(32, 8)>>>(Wq, Wk, Wv);

    dim3 gg(MROWS / 256, EMB / 64, 3);    // (32, 12, 3)
    gemm_fp16_kernel<<<gg, 256, GEMM_SMEM>>>(bq, bk, bv);

    dim3 ga(SEQ / 64, NHEAD, BATCH);
    attn_mma_kernel<<<ga, 128, AT_SMEM>>>(out);
}

// round 14
// speedup vs baseline: 1.0054x; 1.0054x over previous
#include <cuda_runtime.h>
#include <cuda_fp16.h>
#include <cuda_bf16.h>
#include <cstdint>

typedef unsigned long long u64;
typedef unsigned int u32;

#define SEQ   4096
#define BATCH 2
#define EMB   768
#define NHEAD 12
#define HDIM  64
#define HALFW 256
#define MROWS (SEQ * BATCH)   // 8192

// q scaled by 0.125 * log2(e) so softmax can use exp2
#define QSCALE 0.18033688011112042f

// ---------------- device scratch ----------------
__device__ __nv_bfloat16 g_qkvh[3][(size_t)BATCH * NHEAD * SEQ * HDIM];
__device__ __nv_bfloat16 g_qkvl[3][(size_t)BATCH * NHEAD * SEQ * HDIM];
__device__ __half g_xh[(size_t)MROWS * EMB];            // X fp16
__device__ __half g_wt[3][(size_t)EMB * EMB];           // W^T fp16 [n][k]

// ---------------- PTX helpers ----------------
__device__ __forceinline__ u32 smem_u32(const void* p) {
    u32 a;
    asm("{ .reg .u64 t; cvta.to.shared.u64 t, %1; cvt.u32.u64 %0, t; }" : "=r"(a) : "l"(p));
    return a;
}
__device__ __forceinline__ void cp_async16(u32 dst, const void* src) {
    asm volatile("cp.async.cg.shared.global [%0], [%1], 16;" :: "r"(dst), "l"(src) : "memory");
}
__device__ __forceinline__ void cp_commit() {
    asm volatile("cp.async.commit_group;" ::: "memory");
}
template <int N>
__device__ __forceinline__ void cp_wait() {
    asm volatile("cp.async.wait_group %0;" :: "n"(N) : "memory");
}
__device__ __forceinline__ void ldmx4(u32* r, u32 addr) {
    asm volatile("ldmatrix.sync.aligned.m8n8.x4.shared.b16 {%0,%1,%2,%3}, [%4];"
                 : "=r"(r[0]), "=r"(r[1]), "=r"(r[2]), "=r"(r[3]) : "r"(addr));
}
__device__ __forceinline__ void ldmx4t(u32* r, u32 addr) {
    asm volatile("ldmatrix.sync.aligned.m8n8.x4.trans.shared.b16 {%0,%1,%2,%3}, [%4];"
                 : "=r"(r[0]), "=r"(r[1]), "=r"(r[2]), "=r"(r[3]) : "r"(addr));
}
// bf16 mma (attention, 3-term split)
__device__ __forceinline__ void mma16816(float* c, const u32* a, u32 b0, u32 b1) {
    asm volatile(
        "mma.sync.aligned.m16n8k16.row.col.f32.bf16.bf16.f32 "
        "{%0,%1,%2,%3}, {%4,%5,%6,%7}, {%8,%9}, {%0,%1,%2,%3};"
        : "+f"(c[0]), "+f"(c[1]), "+f"(c[2]), "+f"(c[3])
        : "r"(a[0]), "r"(a[1]), "r"(a[2]), "r"(a[3]), "r"(b0), "r"(b1));
}
// fp16 mma (GEMM)
__device__ __forceinline__ void mma16816h(float* c, const u32* a, u32 b0, u32 b1) {
    asm volatile(
        "mma.sync.aligned.m16n8k16.row.col.f32.f16.f16.f32 "
        "{%0,%1,%2,%3}, {%4,%5,%6,%7}, {%8,%9}, {%0,%1,%2,%3};"
        : "+f"(c[0]), "+f"(c[1]), "+f"(c[2]), "+f"(c[3])
        : "r"(a[0]), "r"(a[1]), "r"(a[2]), "r"(a[3]), "r"(b0), "r"(b1));
}
__device__ __forceinline__ u32 pack_bf(float lo, float hi) {
    u32 r;
    asm("cvt.rn.bf16x2.f32 %0, %1, %2;" : "=r"(r) : "f"(hi), "f"(lo));
    return r;
}
__device__ __forceinline__ void split_pair(float p0, float p1, u32& h, u32& l) {
    h = pack_bf(p0, p1);
    const float h0 = __uint_as_float(h << 16);
    const float h1 = __uint_as_float(h & 0xffff0000u);
    l = pack_bf(p0 - h0, p1 - h1);
}

// ---------------------------------------------------------------------------
__global__ __launch_bounds__(256) void conv_x_kernel(const float* __restrict__ X) {
    const size_t i = (size_t)blockIdx.x * 256 + threadIdx.x;
    if (i >= (size_t)MROWS * EMB) return;
    g_xh[i] = __float2half_rn(X[i]);
}

__global__ __launch_bounds__(256) void conv_w_kernel(
    const float* __restrict__ Wq, const float* __restrict__ Wk,
    const float* __restrict__ Wv)
{
    __shared__ float t[32][33];
    const int z = blockIdx.z;
    const float* W = (z == 0) ? Wq : (z == 1) ? Wk : Wv;
    const int n0 = blockIdx.x * 32;
    const int k0 = blockIdx.y * 32;
    const int tx = threadIdx.x, ty = threadIdx.y;
#pragma unroll
    for (int i = 0; i < 4; i++) {
        const int kk = ty + i * 8;
        t[kk][tx] = W[(size_t)(k0 + kk) * EMB + n0 + tx];
    }
    __syncthreads();
#pragma unroll
    for (int i = 0; i < 4; i++) {
        const int nn = ty + i * 8;
        g_wt[z][(size_t)(n0 + nn) * EMB + k0 + tx] = __float2half_rn(t[tx][nn]);
    }
}

// ---------------------------------------------------------------------------
// fp16 single-term QKV GEMM — exact R10 config (CTA 128x64, proven fastest).
// Epilogue: bf16 hi/lo residual pairs; q carries QSCALE (log2e folded).
// ---------------------------------------------------------------------------
#define BK        32
#define ROWB      80
#define ATILE_B   (128 * ROWB)
#define BTILE_B   (64 * ROWB)
#define STAGE_B   (ATILE_B + BTILE_B)        // 15360
#define NSTAGE    3
#define GEMM_SMEM (NSTAGE * STAGE_B)         // 46080
#define NCHUNK    (EMB / BK)                 // 24
#define OFF_A     0
#define OFF_B     ATILE_B

__global__ __launch_bounds__(256, 2)
void gemm_fp16_kernel(const float* __restrict__ bq, const float* __restrict__ bk_,
                      const float* __restrict__ bv)
{
    extern __shared__ __align__(1024) char smem[];
    __shared__ float bias_sh[64];

    const int tid = threadIdx.x;
    const int wid = tid >> 5;
    const int lid = tid & 31;
    const int wm = wid >> 1;
    const int wn = wid & 1;
    const int which = blockIdx.z;
    const int m0 = blockIdx.x * 128;
    const int n0 = blockIdx.y * 64;

    const u32 sb = smem_u32(smem);

    const float* bias = (which == 0) ? bq : (which == 1) ? bk_ : bv;
    if (tid < 64) bias_sh[tid] = bias[n0 + tid];

    const __half* srcA = g_xh + (size_t)m0 * EMB;
    const __half* srcB = g_wt[which] + (size_t)n0 * EMB;

    u32 aoff[2];
#pragma unroll
    for (int mi = 0; mi < 2; mi++)
        aoff[mi] = (u32)((wm * 32 + mi * 16 + (lid & 15)) * ROWB + (lid >> 4) * 16);
    u32 boff[2];
#pragma unroll
    for (int j = 0; j < 2; j++)
        boff[j] = (u32)((wn * 32 + j * 16 + ((lid >> 4) & 1) * 8 + (lid & 7)) * ROWB
                        + ((lid >> 3) & 1) * 16);

    float acc[2][4][4];
#pragma unroll
    for (int mi = 0; mi < 2; mi++)
#pragma unroll
        for (int ni = 0; ni < 4; ni++)
#pragma unroll
            for (int q = 0; q < 4; q++) acc[mi][ni][q] = 0.0f;

    auto load_chunk = [&](int c, int s) {
        const int k0 = c * BK;
        const u32 stage = sb + s * STAGE_B;
#pragma unroll
        for (int i = 0; i < 2; i++) {
            const int g   = tid + i * 256;
            const int row = g >> 2;
            const int prt = g & 3;
            cp_async16(stage + OFF_A + row * ROWB + prt * 16,
                       srcA + (size_t)row * EMB + k0 + prt * 8);
        }
        {
            const int row = tid >> 2;
            const int prt = tid & 3;
            cp_async16(stage + OFF_B + row * ROWB + prt * 16,
                       srcB + (size_t)row * EMB + k0 + prt * 8);
        }
        cp_commit();
    };

    auto compute_chunk = [&](int s) {
        const u32 stage = sb + s * STAGE_B;
        const u32 aB = stage + OFF_A, bB = stage + OFF_B;
#pragma unroll
        for (int ks = 0; ks < 2; ks++) {
            const u32 kadv = ks * 32;
            u32 af[2][4], bf[2][4];
#pragma unroll
            for (int mi = 0; mi < 2; mi++) ldmx4(af[mi], aB + aoff[mi] + kadv);
#pragma unroll
            for (int j = 0; j < 2; j++)    ldmx4(bf[j], bB + boff[j] + kadv);
#pragma unroll
            for (int mi = 0; mi < 2; mi++)
#pragma unroll
                for (int ni = 0; ni < 4; ni++) {
                    const int j = ni >> 1, e = (ni & 1) * 2;
                    mma16816h(acc[mi][ni], af[mi], bf[j][e], bf[j][e + 1]);
                }
        }
    };

    load_chunk(0, 0);
    load_chunk(1, 1);
    for (int c = 0; c < NCHUNK; c++) {
        cp_wait<1>();
        __syncthreads();
        if (c + 2 < NCHUNK) load_chunk(c + 2, (c + 2) % NSTAGE);
        compute_chunk(c % NSTAGE);
    }
    __syncthreads();

    const float scale = (which == 0) ? QSCALE : 1.0f;
    const int row_in_q = lid >> 2;
    const int col_pair = (lid & 3) * 2;
    const int h = n0 >> 6;
#pragma unroll
    for (int mi = 0; mi < 2; mi++) {
#pragma unroll
        for (int ni = 0; ni < 4; ni++) {
            const int ncol = wn * 32 + ni * 8 + col_pair;
            const int d = (n0 + ncol) & 63;
            const float b0v = bias_sh[ncol], b1v = bias_sh[ncol + 1];
#pragma unroll
            for (int half = 0; half < 2; half++) {
                const int m = m0 + wm * 32 + mi * 16 + row_in_q + half * 8;
                const int s_ = m >> 1;
                const int b_ = m & 1;
                const float v0 = (acc[mi][ni][half * 2 + 0] + b0v) * scale;
                const float v1 = (acc[mi][ni][half * 2 + 1] + b1v) * scale;
                u32 hpk, lpk;
                split_pair(v0, v1, hpk, lpk);
                const size_t idx = ((size_t)(b_ * NHEAD + h) * SEQ + s_) * HDIM + d;
                *(u32*)(g_qkvh[which] + idx) = hpk;
                *(u32*)(g_qkvl[which] + idx) = lpk;
            }
        }
    }
}

// ---------------------------------------------------------------------------
// Banded local attention — split-KV warp layout.
// CTA = 256 threads / 8 warps: warp (qg = wid&3, kh = wid>>2) handles 16 query
// rows x 32 keys (half of each 64-key tile). Independent online (m,l,o) per
// warp; one smem merge at the end. 3-term bf16 split everywhere (proven math).
// 16 warps/SM (2 CTAs) vs previous 8 -> ~2x HMMA issue capacity.
// ---------------------------------------------------------------------------
#define AROWB   144
#define ATILE   (64 * AROWB)                 // 9216
#define AQ_B    (2 * ATILE)                  // 18432
#define ASTAGE  (4 * ATILE)                  // 36864
#define AT_SMEM (AQ_B + 2 * ASTAGE)          // 92160
// merge scratch (reuses KV stage area after main loop):
#define MRG_O   AQ_B                          // 4 qg x 16 rows x 64 cols f32 = 16KB
#define MRG_M   (MRG_O + 16384)               // 64 f32
#define MRG_L   (MRG_M + 256)                 // 64 f32

__global__ __launch_bounds__(256, 2)
void attn_mma_kernel(float* __restrict__ out)
{
    extern __shared__ __align__(1024) char smem[];
    const int tid = threadIdx.x;
    const int wid = tid >> 5;
    const int lid = tid & 31;
    const int qg = wid & 3;       // query-row group (16 rows)
    const int kh = wid >> 2;      // key half (0: keys 0-31, 1: keys 32-63)
    const int q0 = blockIdx.x * 64;
    const int h  = blockIdx.y;
    const int b  = blockIdx.z;
    const size_t bh = (size_t)(b * NHEAD + h) * SEQ * HDIM;

    const u32 sb = smem_u32(smem);

    int kt0 = q0 - HALFW; if (kt0 < 0) kt0 = 0;
    int kt1 = q0 + HALFW; if (kt1 > SEQ - 64) kt1 = SEQ - 64;
    const int T = (kt1 - kt0) / 64 + 1;

    // loaders: 256 threads, tile = 512 granules -> 2 per thread
    auto load_q = [&] {
#pragma unroll
        for (int tq = 0; tq < 2; tq++) {
            const __nv_bfloat16* src =
                ((tq == 0) ? g_qkvh[0] : g_qkvl[0]) + bh + (size_t)q0 * HDIM;
            const u32 dstb = sb + tq * ATILE;
#pragma unroll
            for (int i = 0; i < 2; i++) {
                const int g = tid + i * 256;
                const int row = g >> 3, c = g & 7;
                cp_async16(dstb + row * AROWB + c * 16, src + row * HDIM + c * 8);
            }
        }
    };
    auto load_kv = [&](int t, int s) {
        const int kt = kt0 + t * 64;
        const u32 stb = sb + AQ_B + s * ASTAGE;
        const __nv_bfloat16* srcs[4] = {
            g_qkvh[1] + bh + (size_t)kt * HDIM, g_qkvl[1] + bh + (size_t)kt * HDIM,
            g_qkvh[2] + bh + (size_t)kt * HDIM, g_qkvl[2] + bh + (size_t)kt * HDIM };
#pragma unroll
        for (int tt = 0; tt < 4; tt++) {
            const u32 dstb = stb + tt * ATILE;
#pragma unroll
            for (int i = 0; i < 2; i++) {
                const int g = tid + i * 256;
                const int row = g >> 3, c = g & 7;
                cp_async16(dstb + row * AROWB + c * 16, srcs[tt] + row * HDIM + c * 8);
            }
        }
    };

    load_q();
    load_kv(0, 0);
    cp_commit();

    // fragment offsets
    const u32 a_off = (u32)((qg * 16 + (lid & 7) + ((lid >> 3) & 1) * 8) * AROWB
                            + (lid >> 4) * 16);
    u32 kb_off[2];
#pragma unroll
    for (int p = 0; p < 2; p++)
        kb_off[p] = (u32)((kh * 32 + 16 * p + ((lid >> 4) & 1) * 8 + (lid & 7)) * AROWB
                          + ((lid >> 3) & 1) * 16);
    const u32 v_off = (u32)((kh * 32 + (lid & 15)) * AROWB + (lid >> 4) * 16);

    u32 qf[2][4][4];
    float o[8][4];
    float m_r[2] = { -1e30f, -1e30f };
    float l_r[2] = { 0.0f, 0.0f };
#pragma unroll
    for (int ni = 0; ni < 8; ni++)
#pragma unroll
        for (int e = 0; e < 4; e++) o[ni][e] = 0.0f;

    const int r_lane = lid >> 2;
    const int c_lane = (lid & 3) * 2;

    for (int t = 0; t < T; t++) {
        if (t + 1 < T) {
            load_kv(t + 1, (t + 1) & 1);
            cp_commit();
            cp_wait<1>();
        } else {
            cp_wait<0>();
        }
        __syncthreads();

        if (t == 0) {
#pragma unroll
            for (int ks = 0; ks < 4; ks++) {
                ldmx4(qf[0][ks], sb + 0 * ATILE + a_off + ks * 32);
                ldmx4(qf[1][ks], sb + 1 * ATILE + a_off + ks * 32);
            }
        }

        const int kt = kt0 + t * 64;
        const u32 st = sb + AQ_B + (t & 1) * ASTAGE;
        const u32 kHi = st + 0 * ATILE, kLo = st + 1 * ATILE;
        const u32 vHi = st + 2 * ATILE, vLo = st + 3 * ATILE;

        // ---- scores: 16 rows x 32 keys, 3-term bf16 split ----
        float sc[4][4];
#pragma unroll
        for (int ni = 0; ni < 4; ni++)
#pragma unroll
            for (int e = 0; e < 4; e++) sc[ni][e] = 0.0f;

#pragma unroll
        for (int ks = 0; ks < 4; ks++) {
            u32 bh4[2][4], bl4[2][4];
#pragma unroll
            for (int p = 0; p < 2; p++) {
                ldmx4(bh4[p], kHi + kb_off[p] + ks * 32);
                ldmx4(bl4[p], kLo + kb_off[p] + ks * 32);
            }
#pragma unroll
            for (int p = 0; p < 2; p++) {
                mma16816(sc[2 * p + 0], qf[0][ks], bh4[p][0], bh4[p][1]);
                mma16816(sc[2 * p + 1], qf[0][ks], bh4[p][2], bh4[p][3]);
            }
#pragma unroll
            for (int p = 0; p < 2; p++) {
                mma16816(sc[2 * p + 0], qf[0][ks], bl4[p][0], bl4[p][1]);
                mma16816(sc[2 * p + 1], qf[0][ks], bl4[p][2], bl4[p][3]);
            }
#pragma unroll
            for (int p = 0; p < 2; p++) {
                mma16816(sc[2 * p + 0], qf[1][ks], bh4[p][0], bh4[p][1]);
                mma16816(sc[2 * p + 1], qf[1][ks], bh4[p][2], bh4[p][3]);
            }
        }

        // ---- band mask (edge tiles only) ----
        if (kt == q0 - HALFW || kt == q0 + HALFW) {
#pragma unroll
            for (int ni = 0; ni < 4; ni++)
#pragma unroll
                for (int e = 0; e < 4; e++) {
                    const int kc = kt + kh * 32 + ni * 8 + c_lane + (e & 1);
                    const int qa = q0 + qg * 16 + r_lane + ((e >> 1) << 3);
                    const int d = kc - qa;
                    if (d < -HALFW || d > HALFW) sc[ni][e] = -3.0e38f;
                }
        }

        // ---- online softmax over this warp's 32 keys (base-2) ----
        float mx0 = -3.0e38f, mx1 = -3.0e38f;
#pragma unroll
        for (int ni = 0; ni < 4; ni++) {
            mx0 = fmaxf(mx0, fmaxf(sc[ni][0], sc[ni][1]));
            mx1 = fmaxf(mx1, fmaxf(sc[ni][2], sc[ni][3]));
        }
        mx0 = fmaxf(mx0, __shfl_xor_sync(0xffffffffu, mx0, 1));
        mx0 = fmaxf(mx0, __shfl_xor_sync(0xffffffffu, mx0, 2));
        mx1 = fmaxf(mx1, __shfl_xor_sync(0xffffffffu, mx1, 1));
        mx1 = fmaxf(mx1, __shfl_xor_sync(0xffffffffu, mx1, 2));

        const float nm0 = fmaxf(m_r[0], mx0);
        const float nm1 = fmaxf(m_r[1], mx1);
        const float c0 = exp2f(m_r[0] - nm0);
        const float c1 = exp2f(m_r[1] - nm1);
        float s0 = 0.0f, s1 = 0.0f;
#pragma unroll
        for (int ni = 0; ni < 4; ni++) {
            sc[ni][0] = exp2f(sc[ni][0] - nm0); s0 += sc[ni][0];
            sc[ni][1] = exp2f(sc[ni][1] - nm0); s0 += sc[ni][1];
            sc[ni][2] = exp2f(sc[ni][2] - nm1); s1 += sc[ni][2];
            sc[ni][3] = exp2f(sc[ni][3] - nm1); s1 += sc[ni][3];
        }
        s0 += __shfl_xor_sync(0xffffffffu, s0, 1);
        s0 += __shfl_xor_sync(0xffffffffu, s0, 2);
        s1 += __shfl_xor_sync(0xffffffffu, s1, 1);
        s1 += __shfl_xor_sync(0xffffffffu, s1, 2);
        l_r[0] = l_r[0] * c0 + s0; m_r[0] = nm0;
        l_r[1] = l_r[1] * c1 + s1; m_r[1] = nm1;
#pragma unroll
        for (int ni = 0; ni < 8; ni++) {
            o[ni][0] *= c0; o[ni][1] *= c0;
            o[ni][2] *= c1; o[ni][3] *= c1;
        }

        // ---- PV: 3-term bf16 split over this warp's 32 keys (2 k-steps) ----
#pragma unroll
        for (int ks = 0; ks < 2; ks++) {
            u32 ph[4], pl[4];
            split_pair(sc[2 * ks + 0][0], sc[2 * ks + 0][1], ph[0], pl[0]);
            split_pair(sc[2 * ks + 0][2], sc[2 * ks + 0][3], ph[1], pl[1]);
            split_pair(sc[2 * ks + 1][0], sc[2 * ks + 1][1], ph[2], pl[2]);
            split_pair(sc[2 * ks + 1][2], sc[2 * ks + 1][3], ph[3], pl[3]);
            u32 vh4[4][4], vl4[4][4];
#pragma unroll
            for (int p = 0; p < 4; p++) {
                ldmx4t(vh4[p], vHi + v_off + ks * 16 * AROWB + p * 32);
                ldmx4t(vl4[p], vLo + v_off + ks * 16 * AROWB + p * 32);
            }
#pragma unroll
            for (int p = 0; p < 4; p++) {
                mma16816(o[2 * p + 0], ph, vh4[p][0], vh4[p][1]);
                mma16816(o[2 * p + 1], ph, vh4[p][2], vh4[p][3]);
            }
#pragma unroll
            for (int p = 0; p < 4; p++) {
                mma16816(o[2 * p + 0], ph, vl4[p][0], vl4[p][1]);
                mma16816(o[2 * p + 1], ph, vl4[p][2], vl4[p][3]);
            }
#pragma unroll
            for (int p = 0; p < 4; p++) {
                mma16816(o[2 * p + 0], pl, vh4[p][0], vh4[p][1]);
                mma16816(o[2 * p + 1], pl, vh4[p][2], vh4[p][3]);
            }
        }
        __syncthreads();
    }

    // ---- split-KV merge: kh==1 warps publish (o, m, l); kh==0 combine ----
    if (kh == 1) {
#pragma unroll
        for (int ni = 0; ni < 8; ni++)
#pragma unroll
            for (int e = 0; e < 4; e++) {
                const int rloc = r_lane + ((e >> 1) << 3);
                const int col  = ni * 8 + c_lane + (e & 1);
                *(float*)(smem + MRG_O + (((qg * 16 + rloc) * 64) + col) * 4) = o[ni][e];
            }
        if ((lid & 3) == 0) {
            *(float*)(smem + MRG_M + (qg * 16 + r_lane) * 4)     = m_r[0];
            *(float*)(smem + MRG_M + (qg * 16 + r_lane + 8) * 4) = m_r[1];
            *(float*)(smem + MRG_L + (qg * 16 + r_lane) * 4)     = l_r[0];
            *(float*)(smem + MRG_L + (qg * 16 + r_lane + 8) * 4) = l_r[1];
        }
    }
    __syncthreads();

    if (kh == 0) {
        const float pm0 = *(float*)(smem + MRG_M + (qg * 16 + r_lane) * 4);
        const float pm1 = *(float*)(smem + MRG_M + (qg * 16 + r_lane + 8) * 4);
        const float plv0 = *(float*)(smem + MRG_L + (qg * 16 + r_lane) * 4);
        const float plv1 = *(float*)(smem + MRG_L + (qg * 16 + r_lane + 8) * 4);
        const float nm0 = fmaxf(m_r[0], pm0);
        const float nm1 = fmaxf(m_r[1], pm1);
        const float a0 = exp2f(m_r[0] - nm0), b0 = exp2f(pm0 - nm0);
        const float a1 = exp2f(m_r[1] - nm1), b1 = exp2f(pm1 - nm1);
        const float inv0 = 1.0f / (l_r[0] * a0 + plv0 * b0);
        const float inv1 = 1.0f / (l_r[1] * a1 + plv1 * b1);

        const int s_row0 = q0 + qg * 16 + r_lane;
#pragma unroll
        for (int ni = 0; ni < 8; ni++) {
            const int col0 = ni * 8 + c_lane;
            const float po00 = *(float*)(smem + MRG_O + (((qg * 16 + r_lane) * 64) + col0) * 4);
            const float po01 = *(float*)(smem + MRG_O + (((qg * 16 + r_lane) * 64) + col0 + 1) * 4);
            const float po10 = *(float*)(smem + MRG_O + (((qg * 16 + r_lane + 8) * 64) + col0) * 4);
            const float po11 = *(float*)(smem + MRG_O + (((qg * 16 + r_lane + 8) * 64) + col0 + 1) * 4);
            const size_t base = (size_t)b * EMB + h * HDIM + col0;
            float2 r0, r1;
            r0.x = (o[ni][0] * a0 + po00 * b0) * inv0;
            r0.y = (o[ni][1] * a0 + po01 * b0) * inv0;
            r1.x = (o[ni][2] * a1 + po10 * b1) * inv1;
            r1.y = (o[ni][3] * a1 + po11 * b1) * inv1;
            *(float2*)(out + (size_t)s_row0 * (BATCH * EMB) + base) = r0;
            *(float2*)(out + (size_t)(s_row0 + 8) * (BATCH * EMB) + base) = r1;
        }
    }
}

extern "C" void kernel_launch(void* const* d_in, const int* in_sizes, int n_in,
                              void* d_out, int out_size) {
    (void)in_sizes; (void)n_in; (void)out_size;
    const float* X  = (const float*)d_in[0];
    const float* Wq = (const float*)d_in[1];
    const float* bq = (const float*)d_in[2];
    const float* Wk = (const float*)d_in[3];
    const float* bk = (const float*)d_in[4];
    const float* Wv = (const float*)d_in[5];
    const float* bv = (const float*)d_in[6];
    float* out = (float*)d_out;

    static int attr_set = 0;
    if (!attr_set) {
        cudaFuncSetAttribute(gemm_fp16_kernel,
                             cudaFuncAttributeMaxDynamicSharedMemorySize, GEMM_SMEM);
        cudaFuncSetAttribute(attn_mma_kernel,
                             cudaFuncAttributeMaxDynamicSharedMemorySize, AT_SMEM);
        attr_set = 1;
    }

    conv_x_kernel<<<(MROWS * EMB + 255) / 256, 256>>>(X);
    conv_w_kernel<<<dim3(24, 24, 3), dim3(32, 8)>>>(Wq, Wk, Wv);

    dim3 gg(MROWS / 128, EMB / 64, 3);    // (64, 12, 3)
    gemm_fp16_kernel<<<gg, 256, GEMM_SMEM>>>(bq, bk, bv);

    dim3 ga(SEQ / 64, NHEAD, BATCH);
    attn_mma_kernel<<<ga, 256, AT_SMEM>>>(out);
}

// round 15
// speedup vs baseline: 1.0911x; 1.0853x over previous
#include <cuda_runtime.h>
#include <cuda_fp16.h>
#include <cuda_bf16.h>
#include <cstdint>

typedef unsigned long long u64;
typedef unsigned int u32;

#define SEQ   4096
#define BATCH 2
#define EMB   768
#define NHEAD 12
#define HDIM  64
#define HALFW 256
#define MROWS (SEQ * BATCH)   // 8192

// q scaled by 0.125 * log2(e) so softmax can use exp2
#define QSCALE 0.18033688011112042f

// ---------------- device scratch ----------------
__device__ __nv_bfloat16 g_qkvh[3][(size_t)BATCH * NHEAD * SEQ * HDIM];
__device__ __nv_bfloat16 g_qkvl[3][(size_t)BATCH * NHEAD * SEQ * HDIM];
__device__ __half g_xh[(size_t)MROWS * EMB];            // X fp16
__device__ __half g_wt[3][(size_t)EMB * EMB];           // W^T fp16 [n][k]

// ---------------- PTX helpers ----------------
__device__ __forceinline__ u32 smem_u32(const void* p) {
    u32 a;
    asm("{ .reg .u64 t; cvta.to.shared.u64 t, %1; cvt.u32.u64 %0, t; }" : "=r"(a) : "l"(p));
    return a;
}
__device__ __forceinline__ void cp_async16(u32 dst, const void* src) {
    asm volatile("cp.async.cg.shared.global [%0], [%1], 16;" :: "r"(dst), "l"(src) : "memory");
}
__device__ __forceinline__ void cp_commit() {
    asm volatile("cp.async.commit_group;" ::: "memory");
}
template <int N>
__device__ __forceinline__ void cp_wait() {
    asm volatile("cp.async.wait_group %0;" :: "n"(N) : "memory");
}
__device__ __forceinline__ void ldmx4(u32* r, u32 addr) {
    asm volatile("ldmatrix.sync.aligned.m8n8.x4.shared.b16 {%0,%1,%2,%3}, [%4];"
                 : "=r"(r[0]), "=r"(r[1]), "=r"(r[2]), "=r"(r[3]) : "r"(addr));
}
__device__ __forceinline__ void ldmx4t(u32* r, u32 addr) {
    asm volatile("ldmatrix.sync.aligned.m8n8.x4.trans.shared.b16 {%0,%1,%2,%3}, [%4];"
                 : "=r"(r[0]), "=r"(r[1]), "=r"(r[2]), "=r"(r[3]) : "r"(addr));
}
// bf16 mma (attention, 3-term split)
__device__ __forceinline__ void mma16816(float* c, const u32* a, u32 b0, u32 b1) {
    asm volatile(
        "mma.sync.aligned.m16n8k16.row.col.f32.bf16.bf16.f32 "
        "{%0,%1,%2,%3}, {%4,%5,%6,%7}, {%8,%9}, {%0,%1,%2,%3};"
        : "+f"(c[0]), "+f"(c[1]), "+f"(c[2]), "+f"(c[3])
        : "r"(a[0]), "r"(a[1]), "r"(a[2]), "r"(a[3]), "r"(b0), "r"(b1));
}
// fp16 mma (GEMM)
__device__ __forceinline__ void mma16816h(float* c, const u32* a, u32 b0, u32 b1) {
    asm volatile(
        "mma.sync.aligned.m16n8k16.row.col.f32.f16.f16.f32 "
        "{%0,%1,%2,%3}, {%4,%5,%6,%7}, {%8,%9}, {%0,%1,%2,%3};"
        : "+f"(c[0]), "+f"(c[1]), "+f"(c[2]), "+f"(c[3])
        : "r"(a[0]), "r"(a[1]), "r"(a[2]), "r"(a[3]), "r"(b0), "r"(b1));
}
__device__ __forceinline__ u32 pack_bf(float lo, float hi) {
    u32 r;
    asm("cvt.rn.bf16x2.f32 %0, %1, %2;" : "=r"(r) : "f"(hi), "f"(lo));
    return r;
}
__device__ __forceinline__ void split_pair(float p0, float p1, u32& h, u32& l) {
    h = pack_bf(p0, p1);
    const float h0 = __uint_as_float(h << 16);
    const float h1 = __uint_as_float(h & 0xffff0000u);
    l = pack_bf(p0 - h0, p1 - h1);
}

// ---------------------------------------------------------------------------
__global__ __launch_bounds__(256) void conv_x_kernel(const float* __restrict__ X) {
    const size_t i = (size_t)blockIdx.x * 256 + threadIdx.x;
    if (i >= (size_t)MROWS * EMB) return;
    g_xh[i] = __float2half_rn(X[i]);
}

__global__ __launch_bounds__(256) void conv_w_kernel(
    const float* __restrict__ Wq, const float* __restrict__ Wk,
    const float* __restrict__ Wv)
{
    __shared__ float t[32][33];
    const int z = blockIdx.z;
    const float* W = (z == 0) ? Wq : (z == 1) ? Wk : Wv;
    const int n0 = blockIdx.x * 32;
    const int k0 = blockIdx.y * 32;
    const int tx = threadIdx.x, ty = threadIdx.y;
#pragma unroll
    for (int i = 0; i < 4; i++) {
        const int kk = ty + i * 8;
        t[kk][tx] = W[(size_t)(k0 + kk) * EMB + n0 + tx];
    }
    __syncthreads();
#pragma unroll
    for (int i = 0; i < 4; i++) {
        const int nn = ty + i * 8;
        g_wt[z][(size_t)(n0 + nn) * EMB + k0 + tx] = __float2half_rn(t[tx][nn]);
    }
}

// ---------------------------------------------------------------------------
// fp16 single-term QKV GEMM. CTA 128x64, 8 warps (4Mx2N), warp tile 32x32.
// BK=64: 12 chunks (half the barriers of BK=32), 32 HMMA/warp per interval.
// Rows padded to 144B (128B data + 16B) -> conflict-free ldmatrix (same
// geometry as the attention tiles). 3-stage cp.async ring, 2 CTAs/SM.
// ---------------------------------------------------------------------------
#define BK        64
#define ROWB      144
#define ATILE_B   (128 * ROWB)               // 18432
#define BTILE_B   (64 * ROWB)                // 9216
#define STAGE_B   (ATILE_B + BTILE_B)        // 27648
#define NSTAGE    3
#define GEMM_SMEM (NSTAGE * STAGE_B)         // 82944
#define NCHUNK    (EMB / BK)                 // 12
#define OFF_A     0
#define OFF_B     ATILE_B

__global__ __launch_bounds__(256, 2)
void gemm_fp16_kernel(const float* __restrict__ bq, const float* __restrict__ bk_,
                      const float* __restrict__ bv)
{
    extern __shared__ __align__(1024) char smem[];
    __shared__ float bias_sh[64];

    const int tid = threadIdx.x;
    const int wid = tid >> 5;
    const int lid = tid & 31;
    const int wm = wid >> 1;        // 0..3 (32-row slab)
    const int wn = wid & 1;         // 0..1 (32-col slab)
    const int which = blockIdx.z;
    const int m0 = blockIdx.x * 128;
    const int n0 = blockIdx.y * 64;

    const u32 sb = smem_u32(smem);

    const float* bias = (which == 0) ? bq : (which == 1) ? bk_ : bv;
    if (tid < 64) bias_sh[tid] = bias[n0 + tid];

    const __half* srcA = g_xh + (size_t)m0 * EMB;
    const __half* srcB = g_wt[which] + (size_t)n0 * EMB;

    u32 aoff[2];
#pragma unroll
    for (int mi = 0; mi < 2; mi++)
        aoff[mi] = (u32)((wm * 32 + mi * 16 + (lid & 15)) * ROWB + (lid >> 4) * 16);
    u32 boff[2];
#pragma unroll
    for (int j = 0; j < 2; j++)
        boff[j] = (u32)((wn * 32 + j * 16 + ((lid >> 4) & 1) * 8 + (lid & 7)) * ROWB
                        + ((lid >> 3) & 1) * 16);

    float acc[2][4][4];
#pragma unroll
    for (int mi = 0; mi < 2; mi++)
#pragma unroll
        for (int ni = 0; ni < 4; ni++)
#pragma unroll
            for (int q = 0; q < 4; q++) acc[mi][ni][q] = 0.0f;

    // chunk: A = 128 rows x 8 granules (1024; 4/thread), B = 64 x 8 (512; 2/thread)
    auto load_chunk = [&](int c, int s) {
        const int k0 = c * BK;
        const u32 stage = sb + s * STAGE_B;
#pragma unroll
        for (int i = 0; i < 4; i++) {
            const int g   = tid + i * 256;
            const int row = g >> 3;
            const int prt = g & 7;
            cp_async16(stage + OFF_A + row * ROWB + prt * 16,
                       srcA + (size_t)row * EMB + k0 + prt * 8);
        }
#pragma unroll
        for (int i = 0; i < 2; i++) {
            const int g   = tid + i * 256;
            const int row = g >> 3;
            const int prt = g & 7;
            cp_async16(stage + OFF_B + row * ROWB + prt * 16,
                       srcB + (size_t)row * EMB + k0 + prt * 8);
        }
        cp_commit();
    };

    auto compute_chunk = [&](int s) {
        const u32 stage = sb + s * STAGE_B;
        const u32 aB = stage + OFF_A, bB = stage + OFF_B;
#pragma unroll
        for (int ks = 0; ks < 4; ks++) {        // 4 k16 steps per 64-K chunk
            const u32 kadv = ks * 32;
            u32 af[2][4], bf[2][4];
#pragma unroll
            for (int mi = 0; mi < 2; mi++) ldmx4(af[mi], aB + aoff[mi] + kadv);
#pragma unroll
            for (int j = 0; j < 2; j++)    ldmx4(bf[j], bB + boff[j] + kadv);
#pragma unroll
            for (int mi = 0; mi < 2; mi++)
#pragma unroll
                for (int ni = 0; ni < 4; ni++) {
                    const int j = ni >> 1, e = (ni & 1) * 2;
                    mma16816h(acc[mi][ni], af[mi], bf[j][e], bf[j][e + 1]);
                }
        }
    };

    load_chunk(0, 0);
    load_chunk(1, 1);
    for (int c = 0; c < NCHUNK; c++) {
        cp_wait<1>();
        __syncthreads();
        if (c + 2 < NCHUNK) load_chunk(c + 2, (c + 2) % NSTAGE);
        compute_chunk(c % NSTAGE);
    }
    __syncthreads();

    const float scale = (which == 0) ? QSCALE : 1.0f;
    const int row_in_q = lid >> 2;
    const int col_pair = (lid & 3) * 2;
    const int h = n0 >> 6;
#pragma unroll
    for (int mi = 0; mi < 2; mi++) {
#pragma unroll
        for (int ni = 0; ni < 4; ni++) {
            const int ncol = wn * 32 + ni * 8 + col_pair;
            const int d = (n0 + ncol) & 63;
            const float b0v = bias_sh[ncol], b1v = bias_sh[ncol + 1];
#pragma unroll
            for (int half = 0; half < 2; half++) {
                const int m = m0 + wm * 32 + mi * 16 + row_in_q + half * 8;
                const int s_ = m >> 1;
                const int b_ = m & 1;
                const float v0 = (acc[mi][ni][half * 2 + 0] + b0v) * scale;
                const float v1 = (acc[mi][ni][half * 2 + 1] + b1v) * scale;
                u32 hpk, lpk;
                split_pair(v0, v1, hpk, lpk);
                const size_t idx = ((size_t)(b_ * NHEAD + h) * SEQ + s_) * HDIM + d;
                *(u32*)(g_qkvh[which] + idx) = hpk;
                *(u32*)(g_qkvl[which] + idx) = lpk;
            }
        }
    }
}

// ---------------------------------------------------------------------------
// Banded local attention — R13 exact (best measured: 122.7us, rel_err 3.25e-4).
// 3-term bf16 split on scores AND PV; exp2 softmax (q carries log2e).
// ---------------------------------------------------------------------------
#define AROWB   144
#define ATILE   (64 * AROWB)
#define AQ_B    (2 * ATILE)
#define ASTAGE  (4 * ATILE)
#define AT_SMEM (AQ_B + 2 * ASTAGE)          // 92160

__global__ __launch_bounds__(128, 2)
void attn_mma_kernel(float* __restrict__ out)
{
    extern __shared__ __align__(1024) char smem[];
    const int tid = threadIdx.x;
    const int wid = tid >> 5;
    const int lid = tid & 31;
    const int q0 = blockIdx.x * 64;
    const int h  = blockIdx.y;
    const int b  = blockIdx.z;
    const size_t bh = (size_t)(b * NHEAD + h) * SEQ * HDIM;

    const u32 sb = smem_u32(smem);

    int kt0 = q0 - HALFW; if (kt0 < 0) kt0 = 0;
    int kt1 = q0 + HALFW; if (kt1 > SEQ - 64) kt1 = SEQ - 64;
    const int T = (kt1 - kt0) / 64 + 1;

    auto load_q = [&] {
#pragma unroll
        for (int tq = 0; tq < 2; tq++) {
            const __nv_bfloat16* src =
                ((tq == 0) ? g_qkvh[0] : g_qkvl[0]) + bh + (size_t)q0 * HDIM;
            const u32 dstb = sb + tq * ATILE;
#pragma unroll
            for (int i = 0; i < 4; i++) {
                const int g = tid + i * 128;
                const int row = g >> 3, c = g & 7;
                cp_async16(dstb + row * AROWB + c * 16, src + row * HDIM + c * 8);
            }
        }
    };
    auto load_kv = [&](int t, int s) {
        const int kt = kt0 + t * 64;
        const u32 stb = sb + AQ_B + s * ASTAGE;
        const __nv_bfloat16* srcs[4] = {
            g_qkvh[1] + bh + (size_t)kt * HDIM, g_qkvl[1] + bh + (size_t)kt * HDIM,
            g_qkvh[2] + bh + (size_t)kt * HDIM, g_qkvl[2] + bh + (size_t)kt * HDIM };
#pragma unroll
        for (int tt = 0; tt < 4; tt++) {
            const u32 dstb = stb + tt * ATILE;
#pragma unroll
            for (int i = 0; i < 4; i++) {
                const int g = tid + i * 128;
                const int row = g >> 3, c = g & 7;
                cp_async16(dstb + row * AROWB + c * 16, srcs[tt] + row * HDIM + c * 8);
            }
        }
    };

    load_q();
    load_kv(0, 0);
    cp_commit();

    const u32 a_off = (u32)((wid * 16 + (lid & 7) + ((lid >> 3) & 1) * 8) * AROWB
                            + (lid >> 4) * 16);
    u32 kb_off[4];
#pragma unroll
    for (int p = 0; p < 4; p++)
        kb_off[p] = (u32)((16 * p + ((lid >> 4) & 1) * 8 + (lid & 7)) * AROWB
                          + ((lid >> 3) & 1) * 16);
    const u32 v_off = (u32)((lid & 15) * AROWB + (lid >> 4) * 16);

    u32 qf[2][4][4];
    float o[8][4];
    float m_r[2] = { -1e30f, -1e30f };
    float l_r[2] = { 0.0f, 0.0f };
#pragma unroll
    for (int ni = 0; ni < 8; ni++)
#pragma unroll
        for (int e = 0; e < 4; e++) o[ni][e] = 0.0f;

    const int r_lane = lid >> 2;
    const int c_lane = (lid & 3) * 2;

    for (int t = 0; t < T; t++) {
        if (t + 1 < T) {
            load_kv(t + 1, (t + 1) & 1);
            cp_commit();
            cp_wait<1>();
        } else {
            cp_wait<0>();
        }
        __syncthreads();

        if (t == 0) {
#pragma unroll
            for (int ks = 0; ks < 4; ks++) {
                ldmx4(qf[0][ks], sb + 0 * ATILE + a_off + ks * 32);
                ldmx4(qf[1][ks], sb + 1 * ATILE + a_off + ks * 32);
            }
        }

        const int kt = kt0 + t * 64;
        const u32 st = sb + AQ_B + (t & 1) * ASTAGE;
        const u32 kHi = st + 0 * ATILE, kLo = st + 1 * ATILE;
        const u32 vHi = st + 2 * ATILE, vLo = st + 3 * ATILE;

        float sc[8][4];
#pragma unroll
        for (int ni = 0; ni < 8; ni++)
#pragma unroll
            for (int e = 0; e < 4; e++) sc[ni][e] = 0.0f;

#pragma unroll
        for (int ks = 0; ks < 4; ks++) {
            u32 bh4[4][4], bl4[4][4];
#pragma unroll
            for (int p = 0; p < 4; p++) {
                ldmx4(bh4[p], kHi + kb_off[p] + ks * 32);
                ldmx4(bl4[p], kLo + kb_off[p] + ks * 32);
            }
#pragma unroll
            for (int p = 0; p < 4; p++) {
                mma16816(sc[2 * p + 0], qf[0][ks], bh4[p][0], bh4[p][1]);
                mma16816(sc[2 * p + 1], qf[0][ks], bh4[p][2], bh4[p][3]);
            }
#pragma unroll
            for (int p = 0; p < 4; p++) {
                mma16816(sc[2 * p + 0], qf[0][ks], bl4[p][0], bl4[p][1]);
                mma16816(sc[2 * p + 1], qf[0][ks], bl4[p][2], bl4[p][3]);
            }
#pragma unroll
            for (int p = 0; p < 4; p++) {
                mma16816(sc[2 * p + 0], qf[1][ks], bh4[p][0], bh4[p][1]);
                mma16816(sc[2 * p + 1], qf[1][ks], bh4[p][2], bh4[p][3]);
            }
        }

        if (kt == q0 - HALFW || kt == q0 + HALFW) {
#pragma unroll
            for (int ni = 0; ni < 8; ni++)
#pragma unroll
                for (int e = 0; e < 4; e++) {
                    const int kc = kt + ni * 8 + c_lane + (e & 1);
                    const int qa = q0 + wid * 16 + r_lane + ((e >> 1) << 3);
                    const int d = kc - qa;
                    if (d < -HALFW || d > HALFW) sc[ni][e] = -3.0e38f;
                }
        }

        float mx0 = -3.0e38f, mx1 = -3.0e38f;
#pragma unroll
        for (int ni = 0; ni < 8; ni++) {
            mx0 = fmaxf(mx0, fmaxf(sc[ni][0], sc[ni][1]));
            mx1 = fmaxf(mx1, fmaxf(sc[ni][2], sc[ni][3]));
        }
        mx0 = fmaxf(mx0, __shfl_xor_sync(0xffffffffu, mx0, 1));
        mx0 = fmaxf(mx0, __shfl_xor_sync(0xffffffffu, mx0, 2));
        mx1 = fmaxf(mx1, __shfl_xor_sync(0xffffffffu, mx1, 1));
        mx1 = fmaxf(mx1, __shfl_xor_sync(0xffffffffu, mx1, 2));

        const float nm0 = fmaxf(m_r[0], mx0);
        const float nm1 = fmaxf(m_r[1], mx1);
        const float c0 = exp2f(m_r[0] - nm0);
        const float c1 = exp2f(m_r[1] - nm1);
        float s0 = 0.0f, s1 = 0.0f;
#pragma unroll
        for (int ni = 0; ni < 8; ni++) {
            sc[ni][0] = exp2f(sc[ni][0] - nm0); s0 += sc[ni][0];
            sc[ni][1] = exp2f(sc[ni][1] - nm0); s0 += sc[ni][1];
            sc[ni][2] = exp2f(sc[ni][2] - nm1); s1 += sc[ni][2];
            sc[ni][3] = exp2f(sc[ni][3] - nm1); s1 += sc[ni][3];
        }
        s0 += __shfl_xor_sync(0xffffffffu, s0, 1);
        s0 += __shfl_xor_sync(0xffffffffu, s0, 2);
        s1 += __shfl_xor_sync(0xffffffffu, s1, 1);
        s1 += __shfl_xor_sync(0xffffffffu, s1, 2);
        l_r[0] = l_r[0] * c0 + s0; m_r[0] = nm0;
        l_r[1] = l_r[1] * c1 + s1; m_r[1] = nm1;
#pragma unroll
        for (int ni = 0; ni < 8; ni++) {
            o[ni][0] *= c0; o[ni][1] *= c0;
            o[ni][2] *= c1; o[ni][3] *= c1;
        }

#pragma unroll
        for (int ks = 0; ks < 4; ks++) {
            u32 ph[4], pl[4];
            split_pair(sc[2 * ks + 0][0], sc[2 * ks + 0][1], ph[0], pl[0]);
            split_pair(sc[2 * ks + 0][2], sc[2 * ks + 0][3], ph[1], pl[1]);
            split_pair(sc[2 * ks + 1][0], sc[2 * ks + 1][1], ph[2], pl[2]);
            split_pair(sc[2 * ks + 1][2], sc[2 * ks + 1][3], ph[3], pl[3]);
            u32 vh4[4][4], vl4[4][4];
#pragma unroll
            for (int p = 0; p < 4; p++) {
                ldmx4t(vh4[p], vHi + v_off + ks * 16 * AROWB + p * 32);
                ldmx4t(vl4[p], vLo + v_off + ks * 16 * AROWB + p * 32);
            }
#pragma unroll
            for (int p = 0; p < 4; p++) {
                mma16816(o[2 * p + 0], ph, vh4[p][0], vh4[p][1]);
                mma16816(o[2 * p + 1], ph, vh4[p][2], vh4[p][3]);
            }
#pragma unroll
            for (int p = 0; p < 4; p++) {
                mma16816(o[2 * p + 0], ph, vl4[p][0], vl4[p][1]);
                mma16816(o[2 * p + 1], ph, vl4[p][2], vl4[p][3]);
            }
#pragma unroll
            for (int p = 0; p < 4; p++) {
                mma16816(o[2 * p + 0], pl, vh4[p][0], vh4[p][1]);
                mma16816(o[2 * p + 1], pl, vh4[p][2], vh4[p][3]);
            }
        }
        __syncthreads();
    }

    const float inv0 = 1.0f / l_r[0];
    const float inv1 = 1.0f / l_r[1];
    const int s_row0 = q0 + wid * 16 + r_lane;
#pragma unroll
    for (int ni = 0; ni < 8; ni++) {
        const int dcol = ni * 8 + c_lane;
        const size_t base = (size_t)b * EMB + h * HDIM + dcol;
        float2 r0, r1;
        r0.x = o[ni][0] * inv0; r0.y = o[ni][1] * inv0;
        r1.x = o[ni][2] * inv1; r1.y = o[ni][3] * inv1;
        *(float2*)(out + (size_t)s_row0 * (BATCH * EMB) + base) = r0;
        *(float2*)(out + (size_t)(s_row0 + 8) * (BATCH * EMB) + base) = r1;
    }
}

extern "C" void kernel_launch(void* const* d_in, const int* in_sizes, int n_in,
                              void* d_out, int out_size) {
    (void)in_sizes; (void)n_in; (void)out_size;
    const float* X  = (const float*)d_in[0];
    const float* Wq = (const float*)d_in[1];
    const float* bq = (const float*)d_in[2];
    const float* Wk = (const float*)d_in[3];
    const float* bk = (const float*)d_in[4];
    const float* Wv = (const float*)d_in[5];
    const float* bv = (const float*)d_in[6];
    float* out = (float*)d_out;

    static int attr_set = 0;
    if (!attr_set) {
        cudaFuncSetAttribute(gemm_fp16_kernel,
                             cudaFuncAttributeMaxDynamicSharedMemorySize, GEMM_SMEM);
        cudaFuncSetAttribute(attn_mma_kernel,
                             cudaFuncAttributeMaxDynamicSharedMemorySize, AT_SMEM);
        attr_set = 1;
    }

    conv_x_kernel<<<(MROWS * EMB + 255) / 256, 256>>>(X);
    conv_w_kernel<<<dim3(24, 24, 3), dim3(32, 8)>>>(Wq, Wk, Wv);

    dim3 gg(MROWS / 128, EMB / 64, 3);    // (64, 12, 3)
    gemm_fp16_kernel<<<gg, 256, GEMM_SMEM>>>(bq, bk, bv);

    dim3 ga(SEQ / 64, NHEAD, BATCH);
    attn_mma_kernel<<<ga, 128, AT_SMEM>>>(out);
}